// round 14
// baseline (speedup 1.0000x reference)
#include <cuda_runtime.h>
#include <cuda_bf16.h>
#include <cuda_fp16.h>
#include <stdint.h>

#define BB 2
#define EE 512
#define NN 4096
#define MM 4096

typedef unsigned long long u64;
typedef unsigned int u32;

// ---- scratch ---------------------------------------------------------------
__device__ __nv_bfloat16 g_Qhi[BB * NN * EE], g_Qlo[BB * NN * EE];
__device__ __nv_bfloat16 g_Khi[BB * MM * EE], g_Klo[BB * MM * EE];
__device__ __nv_bfloat16 g_XQhi[BB * NN * EE], g_XQlo[BB * NN * EE];
__device__ __nv_bfloat16 g_XKhi[BB * MM * EE], g_XKlo[BB * MM * EE];
__device__ __nv_bfloat16 g_Whi[2 * EE * EE], g_Wlo[2 * EE * EE];
__device__ float g_kk[BB * MM];
__device__ __half g_est[(size_t)BB * NN * MM];   // approximate logits (64 MB)

// ---- PTX helpers (portable, no 'a'-features) -------------------------------
__device__ __forceinline__ u32 smem_u32(const void* p) {
    u32 a;
    asm("{ .reg .u64 t; cvta.to.shared.u64 t, %1; cvt.u32.u64 %0, t; }" : "=r"(a) : "l"(p));
    return a;
}
__device__ __forceinline__ void cp16(u32 dst, const void* src) {
    asm volatile("cp.async.cg.shared.global [%0], [%1], 16;" :: "r"(dst), "l"(src) : "memory");
}
#define CP_COMMIT() asm volatile("cp.async.commit_group;" ::: "memory")
#define CP_WAIT0()  asm volatile("cp.async.wait_group 0;" ::: "memory")
#define CP_WAIT1()  asm volatile("cp.async.wait_group 1;" ::: "memory")

__device__ __forceinline__ void ldsm4(u32* r, u32 a) {
    asm volatile("ldmatrix.sync.aligned.m8n8.x4.shared.b16 {%0,%1,%2,%3}, [%4];"
                 : "=r"(r[0]), "=r"(r[1]), "=r"(r[2]), "=r"(r[3]) : "r"(a));
}
__device__ __forceinline__ void mma16816(float* c, const u32* a, const u32* b) {
    asm volatile(
        "mma.sync.aligned.m16n8k16.row.col.f32.bf16.bf16.f32 "
        "{%0,%1,%2,%3}, {%4,%5,%6,%7}, {%8,%9}, {%0,%1,%2,%3};"
        : "+f"(c[0]), "+f"(c[1]), "+f"(c[2]), "+f"(c[3])
        : "r"(a[0]), "r"(a[1]), "r"(a[2]), "r"(a[3]), "r"(b[0]), "r"(b[1]));
}
__device__ __forceinline__ u32 packbf(__nv_bfloat16 a, __nv_bfloat16 b) {
    __nv_bfloat162 t; t.x = a; t.y = b;
    return *reinterpret_cast<u32*>(&t);
}

// ---------------------------------------------------------------------------
// split W: [f][e] fp32 -> bf16 hi/lo
// ---------------------------------------------------------------------------
__global__ __launch_bounds__(256) void splitW_kernel(const float* __restrict__ W, int slot)
{
    const int i = (blockIdx.x * 256 + threadIdx.x) * 4;
    float4 v = *(const float4*)(W + i);
    float x[4] = {v.x, v.y, v.z, v.w};
    __nv_bfloat16 h[4]; float l[4];
#pragma unroll
    for (int k = 0; k < 4; ++k) {
        h[k] = __float2bfloat16_rn(x[k]);
        l[k] = x[k] - __bfloat162float(h[k]);
    }
    uint2 ph, pl;
    ph.x = packbf(h[0], h[1]); ph.y = packbf(h[2], h[3]);
    pl.x = packbf(__float2bfloat16_rn(l[0]), __float2bfloat16_rn(l[1]));
    pl.y = packbf(__float2bfloat16_rn(l[2]), __float2bfloat16_rn(l[3]));
    const size_t off = (size_t)slot * EE * EE + i;
    *(uint2*)(g_Whi + off) = ph;
    *(uint2*)(g_Wlo + off) = pl;
}

// ---------------------------------------------------------------------------
// split+transpose X: [b][e][n] fp32 -> bf16 hi/lo [b][n][e]
// ---------------------------------------------------------------------------
__global__ __launch_bounds__(256) void splitX_kernel(const float* __restrict__ X, int which)
{
    __nv_bfloat16* __restrict__ Yh = which ? g_XKhi : g_XQhi;
    __nv_bfloat16* __restrict__ Yl = which ? g_XKlo : g_XQlo;
    __shared__ float tile[64][65];
    const int tid = threadIdx.x;
    const int n0 = blockIdx.x * 64, e0 = blockIdx.y * 64, b = blockIdx.z;
    const float* Xb = X + (size_t)b * EE * NN;

    const int lr = tid >> 4, n4 = tid & 15;
#pragma unroll
    for (int it = 0; it < 4; ++it) {
        const int e = lr + it * 16;
        float4 v = *(const float4*)(Xb + (size_t)(e0 + e) * NN + n0 + n4 * 4);
        tile[e][n4*4+0] = v.x; tile[e][n4*4+1] = v.y;
        tile[e][n4*4+2] = v.z; tile[e][n4*4+3] = v.w;
    }
    __syncthreads();

    const int n = tid >> 2, et = tid & 3;
    u32 hw[8], lw[8];
#pragma unroll
    for (int k = 0; k < 8; ++k) {
        const float a = tile[et*16 + 2*k][n], c = tile[et*16 + 2*k + 1][n];
        __nv_bfloat16 ha = __float2bfloat16_rn(a), hc = __float2bfloat16_rn(c);
        hw[k] = packbf(ha, hc);
        lw[k] = packbf(__float2bfloat16_rn(a - __bfloat162float(ha)),
                       __float2bfloat16_rn(c - __bfloat162float(hc)));
    }
    const size_t base = ((size_t)b * NN + n0 + n) * EE + e0 + et * 16;
    *(uint4*)(Yh + base)     = *(uint4*)(hw);
    *(uint4*)(Yh + base + 8) = *(uint4*)(hw + 4);
    *(uint4*)(Yl + base)     = *(uint4*)(lw);
    *(uint4*)(Yl + base + 8) = *(uint4*)(lw + 4);
}

// ---------------------------------------------------------------------------
// proj via mma (3-term split), warp-autonomous. Unchanged.
// ---------------------------------------------------------------------------
#define QPITCH 1040
#define SM_QH 0
#define SM_QL 33280
#define SM_K  66560
#define KPITCH 80
#define KLO_OFF 10240
#define STAGE 20480
#define SMEM_TOTAL 107520

__global__ __launch_bounds__(256, 2) void projmma_kernel(const float* __restrict__ bias,
                                                         int which)
{
    extern __shared__ char smraw[];
    const u32 S = smem_u32(smraw);
    const int tid = threadIdx.x, kg = tid >> 5, lane = tid & 31;
    const int b = blockIdx.x >> 7, n0 = (blockIdx.x & 127) * 32;
    const int f0 = blockIdx.y * 128;
    const __nv_bfloat16* Axh = which ? g_XKhi : g_XQhi;
    const __nv_bfloat16* Axl = which ? g_XKlo : g_XQlo;
    __nv_bfloat16* Oh = which ? g_Khi : g_Qhi;
    __nv_bfloat16* Ol = which ? g_Klo : g_Qlo;
    const char* Wh = (const char*)(g_Whi + (size_t)which * EE * EE);
    const char* Wl = (const char*)(g_Wlo + (size_t)which * EE * EE);

    {
        const char* ah = (const char*)(Axh + (size_t)(b * NN + n0) * EE);
        const char* al = (const char*)(Axl + (size_t)(b * NN + n0) * EE);
#pragma unroll
        for (int it = 0; it < 8; ++it) {
            const int i = tid + it * 256;
            const int row = i >> 6, g = (i & 63) * 16;
            cp16(S + SM_QH + row * QPITCH + g, ah + row * 1024 + g);
            cp16(S + SM_QL + row * QPITCH + g, al + row * 1024 + g);
        }
        CP_COMMIT(); CP_WAIT0();
        __syncthreads();
    }

    const int laneQrow = (lane & 7) + ((lane >> 3) & 1) * 8;
    const int laneQcolB = (lane >> 4) * 16;
    const int laneKn = (lane & 7) + ((lane >> 4) & 1) * 8;
    const int laneKeB = ((lane >> 3) & 1) * 16;
    u32 qoff[2];
    qoff[0] = (u32)(laneQrow * QPITCH + laneQcolB);
    qoff[1] = qoff[0] + 16 * QPITCH;
    const u32 koff = (u32)((kg * 16 + laneKn) * KPITCH + laneKeB);

    const u32 fko = (u32)((kg * 16 + (lane >> 1)) * KPITCH + (lane & 1) * 32);
    const char* sWh = Wh + (size_t)(f0 + kg * 16 + (lane >> 1)) * 1024 + (lane & 1) * 32;
    const char* sWl = Wl + (size_t)(f0 + kg * 16 + (lane >> 1)) * 1024 + (lane & 1) * 32;

    float acc[2][2][4];
#pragma unroll
    for (int mt = 0; mt < 2; ++mt)
#pragma unroll
        for (int nt = 0; nt < 2; ++nt)
#pragma unroll
            for (int j = 0; j < 4; ++j) acc[mt][nt][j] = 0.f;

    cp16(S + SM_K + fko,                sWh);
    cp16(S + SM_K + fko + 16,           sWh + 16);
    cp16(S + SM_K + KLO_OFF + fko,      sWl);
    cp16(S + SM_K + KLO_OFF + fko + 16, sWl + 16);
    CP_COMMIT();

    for (int cc = 0; cc < 16; ++cc) {
        if (cc < 15) {
            const int nc = cc + 1;
            const u32 dst = S + SM_K + (u32)(nc & 1) * STAGE + fko;
            const size_t go = (size_t)nc * 64;
            cp16(dst,                sWh + go);
            cp16(dst + 16,           sWh + go + 16);
            cp16(dst + KLO_OFF,      sWl + go);
            cp16(dst + KLO_OFF + 16, sWl + go + 16);
            CP_COMMIT();
            CP_WAIT1();
        } else {
            CP_WAIT0();
        }
        __syncwarp();
        const u32 KB = S + SM_K + (u32)(cc & 1) * STAGE;
        const u32 chB = (u32)(cc * 64);
#pragma unroll
        for (int s = 0; s < 2; ++s) {
            const u32 qeB = chB + (u32)(s * 32);
            const u32 keB = (u32)(s * 32);
            u32 ah[2][4], al[2][4], bh[4], bl[4];
#pragma unroll
            for (int mt = 0; mt < 2; ++mt) {
                ldsm4(ah[mt], S + SM_QH + qoff[mt] + qeB);
                ldsm4(al[mt], S + SM_QL + qoff[mt] + qeB);
            }
            ldsm4(bh, KB + koff + keB);
            ldsm4(bl, KB + KLO_OFF + koff + keB);
#pragma unroll
            for (int mt = 0; mt < 2; ++mt) {
                mma16816(acc[mt][0], ah[mt], &bh[0]);
                mma16816(acc[mt][0], ah[mt], &bl[0]);
                mma16816(acc[mt][0], al[mt], &bh[0]);
                mma16816(acc[mt][1], ah[mt], &bh[2]);
                mma16816(acc[mt][1], ah[mt], &bl[2]);
                mma16816(acc[mt][1], al[mt], &bh[2]);
            }
        }
    }

    __syncthreads();
    float bias2[2][2];
#pragma unroll
    for (int nt = 0; nt < 2; ++nt)
#pragma unroll
        for (int j = 0; j < 2; ++j)
            bias2[nt][j] = __ldg(bias + f0 + kg * 16 + nt * 8 + (lane & 3) * 2 + j);
    __nv_bfloat16* sh = (__nv_bfloat16*)(smraw + SM_K);
    __nv_bfloat16* sl = (__nv_bfloat16*)(smraw + SM_K + 8192);
#pragma unroll
    for (int mt = 0; mt < 2; ++mt)
#pragma unroll
        for (int nt = 0; nt < 2; ++nt)
#pragma unroll
            for (int c = 0; c < 4; ++c) {
                const int row = mt * 16 + (lane >> 2) + (c >> 1) * 8;
                const int col = kg * 16 + nt * 8 + (lane & 3) * 2 + (c & 1);
                const float q = acc[mt][nt][c] + bias2[nt][c & 1];
                const __nv_bfloat16 h = __float2bfloat16_rn(q);
                sh[row * 128 + col] = h;
                sl[row * 128 + col] = __float2bfloat16_rn(q - __bfloat162float(h));
            }
    __syncthreads();
    {
        const int row = tid >> 3, seg = tid & 7;
        const size_t gbase = ((size_t)(b * NN + n0 + row)) * EE + f0 + seg * 16;
        const int sbase = row * 128 + seg * 16;
        *(uint4*)(Oh + gbase)     = *(uint4*)(sh + sbase);
        *(uint4*)(Oh + gbase + 8) = *(uint4*)(sh + sbase + 8);
        *(uint4*)(Ol + gbase)     = *(uint4*)(sl + sbase);
        *(uint4*)(Ol + gbase + 8) = *(uint4*)(sl + sbase + 8);
    }
}

// ---------------------------------------------------------------------------
__global__ __launch_bounds__(256) void kk_kernel()
{
    const int row = blockIdx.x * 8 + (threadIdx.x >> 5);
    const int lane = threadIdx.x & 31;
    const uint4* h4 = (const uint4*)(g_Khi + (size_t)row * EE);
    const uint4* l4 = (const uint4*)(g_Klo + (size_t)row * EE);
    float s = 0.f;
#pragma unroll
    for (int it = 0; it < 2; ++it) {
        uint4 h = h4[lane + it * 32], l = l4[lane + it * 32];
        const __nv_bfloat162* hp = (const __nv_bfloat162*)&h;
        const __nv_bfloat162* lp = (const __nv_bfloat162*)&l;
#pragma unroll
        for (int k = 0; k < 4; ++k) {
            float2 fh = __bfloat1622float2(hp[k]);
            float2 fl = __bfloat1622float2(lp[k]);
            float x = fh.x + fl.x, y = fh.y + fl.y;
            s = fmaf(x, x, fmaf(y, y, s));
        }
    }
#pragma unroll
    for (int off = 16; off; off >>= 1) s += __shfl_xor_sync(0xffffffffu, s, off);
    if (lane == 0) g_kk[row] = s;
}

// ---------------------------------------------------------------------------
// Phase 1 (v2 fixed): hi*hi est logits. 64-e chunks (16 mma/step), 3 CTAs/SM.
// grid (256, 4): b = bx>>7, n-tile = bx&127 (32 rows), by = 1024-key split.
// cc < 64: tile = cc>>3 (8 x 128-key tiles), echunk = cc&7 (8 x 64-e chunks).
// ---------------------------------------------------------------------------
#define KP2 144
#define P2_SMK 33280
#define P2_STAGE 18432
#define P2_TOTAL 70144

__global__ __launch_bounds__(256, 3) void est_kernel()
{
    extern __shared__ char smraw[];
    const u32 S = smem_u32(smraw);
    const int tid = threadIdx.x, kg = tid >> 5, lane = tid & 31;
    const int b = blockIdx.x >> 7, n0 = (blockIdx.x & 127) * 32;
    const int mbase = blockIdx.y * 1024;

    {   // Qhi tile fill: 32 rows x 1024 B
        const char* qh = (const char*)(g_Qhi + (size_t)(b * NN + n0) * EE);
#pragma unroll
        for (int it = 0; it < 8; ++it) {
            const int i = tid + it * 256;
            const int row = i >> 6, g = (i & 63) * 16;
            cp16(S + row * QPITCH + g, qh + row * 1024 + g);
        }
        CP_COMMIT(); CP_WAIT0();
        __syncthreads();
    }

    const int laneQrow = (lane & 7) + ((lane >> 3) & 1) * 8;
    const int laneQcolB = (lane >> 4) * 16;
    const int laneKn = (lane & 7) + ((lane >> 4) & 1) * 8;
    const int laneKeB = ((lane >> 3) & 1) * 16;
    u32 qoff[2];
    qoff[0] = (u32)(laneQrow * QPITCH + laneQcolB);
    qoff[1] = qoff[0] + 16 * QPITCH;
    const u32 koff = (u32)((kg * 16 + laneKn) * KP2 + laneKeB);

    // fill: lane owns key (lane>>1), 64-byte half (lane&1) -> 4 cp16 per chunk
    const u32 fko = (u32)((kg * 16 + (lane >> 1)) * KP2 + (lane & 1) * 64);
    const char* src_h = (const char*)g_Khi
        + ((size_t)(b * MM + mbase + kg * 16 + (lane >> 1))) * 1024 + (lane & 1) * 64;

    const float* kkb = g_kk + b * MM + mbase;
    __half* estb = g_est + ((size_t)(b * NN + n0)) * MM + mbase;

    float acc[2][2][4];
#pragma unroll
    for (int mt = 0; mt < 2; ++mt)
#pragma unroll
        for (int nt = 0; nt < 2; ++nt)
#pragma unroll
            for (int j = 0; j < 4; ++j) acc[mt][nt][j] = 0.f;

    {   // prologue: chunk 0 -> stage 0
        const u32 d0 = S + P2_SMK + fko;
        cp16(d0,      src_h);
        cp16(d0 + 16, src_h + 16);
        cp16(d0 + 32, src_h + 32);
        cp16(d0 + 48, src_h + 48);
        CP_COMMIT();
    }

    for (int cc = 0; cc < 64; ++cc) {
        if (cc < 63) {
            const int nc = cc + 1;
            const u32 dst = S + P2_SMK + (u32)(nc & 1) * P2_STAGE + fko;
            const size_t go = (size_t)(nc >> 3) * 131072 + (size_t)(nc & 7) * 128;
            cp16(dst,      src_h + go);
            cp16(dst + 16, src_h + go + 16);
            cp16(dst + 32, src_h + go + 32);
            cp16(dst + 48, src_h + go + 48);
            CP_COMMIT();
            CP_WAIT1();
        } else {
            CP_WAIT0();
        }
        __syncwarp();

        const u32 KB = S + P2_SMK + (u32)(cc & 1) * P2_STAGE;
        const u32 qchB = (u32)((cc & 7) * 128);
#pragma unroll
        for (int s = 0; s < 4; ++s) {
            u32 ah[2][4], bh[4];
            ldsm4(ah[0], S + qoff[0] + qchB + (u32)(s * 32));
            ldsm4(ah[1], S + qoff[1] + qchB + (u32)(s * 32));
            ldsm4(bh, KB + koff + (u32)(s * 32));
#pragma unroll
            for (int mt = 0; mt < 2; ++mt) {
                mma16816(acc[mt][0], ah[mt], &bh[0]);
                mma16816(acc[mt][1], ah[mt], &bh[2]);
            }
        }

        if ((cc & 7) == 7) {
            const int m0 = (cc >> 3) * 128;
            const int c0 = kg * 16 + (lane & 3) * 2;
            const float kk0 = __ldg(kkb + m0 + c0);
            const float kk1 = __ldg(kkb + m0 + c0 + 1);
            const float kk2 = __ldg(kkb + m0 + c0 + 8);
            const float kk3 = __ldg(kkb + m0 + c0 + 9);
#pragma unroll
            for (int mt = 0; mt < 2; ++mt)
#pragma unroll
                for (int h = 0; h < 2; ++h) {
                    const int row = mt * 16 + h * 8 + (lane >> 2);
                    __half* ep = estb + (size_t)row * MM + m0 + c0;
                    float2 fa = make_float2(fmaf(2.f, acc[mt][0][h*2+0], -kk0),
                                            fmaf(2.f, acc[mt][0][h*2+1], -kk1));
                    float2 fb = make_float2(fmaf(2.f, acc[mt][1][h*2+0], -kk2),
                                            fmaf(2.f, acc[mt][1][h*2+1], -kk3));
                    *reinterpret_cast<__half2*>(ep)     = __float22half2_rn(fa);
                    *reinterpret_cast<__half2*>(ep + 8) = __float22half2_rn(fb);
                    acc[mt][0][h*2+0] = 0.f; acc[mt][0][h*2+1] = 0.f;
                    acc[mt][1][h*2+0] = 0.f; acc[mt][1][h*2+1] = 0.f;
                }
        }
    }
}

// ---------------------------------------------------------------------------
// Phase 2: register-cached scan + exact recompute. One warp per q-row.
// ---------------------------------------------------------------------------
__global__ __launch_bounds__(256) void gather_kernel(const float* __restrict__ tgt,
                                                     float* __restrict__ out_corr)
{
    const int w = blockIdx.x * 8 + (threadIdx.x >> 5);   // b*NN + n
    const int lane = threadIdx.x & 31;
    const int b = w >> 12, n = w & (NN - 1);

    float qf[16];
    {
        const uint4* qh = (const uint4*)(g_Qhi + (size_t)w * EE + lane * 16);
        const uint4* ql = (const uint4*)(g_Qlo + (size_t)w * EE + lane * 16);
        uint4 H[2] = {qh[0], qh[1]}, L[2] = {ql[0], ql[1]};
#pragma unroll
        for (int g = 0; g < 2; ++g) {
            const __nv_bfloat162* hp = (const __nv_bfloat162*)&H[g];
            const __nv_bfloat162* lp = (const __nv_bfloat162*)&L[g];
#pragma unroll
            for (int j = 0; j < 4; ++j) {
                float2 fh = __bfloat1622float2(hp[j]);
                float2 fl = __bfloat1622float2(lp[j]);
                qf[g*8 + j*2 + 0] = fh.x + fl.x;
                qf[g*8 + j*2 + 1] = fh.y + fl.y;
            }
        }
    }

    const __half* er = g_est + (size_t)w * MM;
    u32 cache[64];
    float rmax = -1e30f;
#pragma unroll
    for (int it = 0; it < 16; ++it) {
        uint4 v = *(const uint4*)(er + it * 256 + lane * 8);
        cache[it*4+0] = v.x; cache[it*4+1] = v.y;
        cache[it*4+2] = v.z; cache[it*4+3] = v.w;
        const __half2* hp = (const __half2*)&v;
#pragma unroll
        for (int j = 0; j < 4; ++j) {
            float2 f = __half22float2(hp[j]);
            rmax = fmaxf(rmax, fmaxf(f.x, f.y));
        }
    }
#pragma unroll
    for (int off = 16; off; off >>= 1)
        rmax = fmaxf(rmax, __shfl_xor_sync(0xffffffffu, rmax, off));
    const float T = rmax - 25.f;

    const float* kkb = g_kk + b * MM;
    const float* tb  = tgt + (size_t)b * 3 * MM;
    float m = -1e30f, sl = 0.f, o0 = 0.f, o1 = 0.f, o2 = 0.f;

#pragma unroll
    for (int it = 0; it < 16; ++it) {
        u32 mk = 0;
#pragma unroll
        for (int j = 0; j < 4; ++j) {
            float2 f = __half22float2(*(const __half2*)&cache[it*4+j]);
            if (f.x >= T) mk |= 1u << (j*2);
            if (f.y >= T) mk |= 1u << (j*2+1);
        }
        u32 wm = __ballot_sync(0xffffffffu, mk != 0);
        while (wm) {
            const int slane = __ffs(wm) - 1;
            wm &= wm - 1;
            u32 m8 = __shfl_sync(0xffffffffu, mk, slane);
            while (m8) {
                const int bit = __ffs(m8) - 1;
                m8 &= m8 - 1;
                const int kix = it * 256 + slane * 8 + bit;
                const uint4* kh = (const uint4*)(g_Khi + (size_t)(b * MM + kix) * EE + lane * 16);
                const uint4* kl = (const uint4*)(g_Klo + (size_t)(b * MM + kix) * EE + lane * 16);
                uint4 H[2] = {kh[0], kh[1]}, L[2] = {kl[0], kl[1]};
                float d = 0.f;
#pragma unroll
                for (int g = 0; g < 2; ++g) {
                    const __nv_bfloat162* hp = (const __nv_bfloat162*)&H[g];
                    const __nv_bfloat162* lp = (const __nv_bfloat162*)&L[g];
#pragma unroll
                    for (int j = 0; j < 4; ++j) {
                        float2 fh = __bfloat1622float2(hp[j]);
                        float2 fl = __bfloat1622float2(lp[j]);
                        d = fmaf(qf[g*8 + j*2 + 0], fh.x + fl.x, d);
                        d = fmaf(qf[g*8 + j*2 + 1], fh.y + fl.y, d);
                    }
                }
#pragma unroll
                for (int off = 16; off; off >>= 1)
                    d += __shfl_xor_sync(0xffffffffu, d, off);
                if (lane == 0) {
                    const float lg = fmaf(2.f, d, -__ldg(kkb + kix));
                    const float nm = fmaxf(m, lg);
                    const float sc = __expf(m - nm);
                    const float p  = __expf(lg - nm);
                    sl = sl * sc + p;
                    o0 = o0 * sc + p * __ldg(tb + kix);
                    o1 = o1 * sc + p * __ldg(tb + MM + kix);
                    o2 = o2 * sc + p * __ldg(tb + 2 * MM + kix);
                    m = nm;
                }
            }
        }
    }

    if (lane == 0) {
        const float inv = 1.f / sl;
        out_corr[(size_t)b * 3 * NN + n]          = o0 * inv;
        out_corr[(size_t)b * 3 * NN + NN + n]     = o1 * inv;
        out_corr[(size_t)b * 3 * NN + 2 * NN + n] = o2 * inv;
    }
}

__global__ void copy_src_kernel(const float* __restrict__ src, float* __restrict__ out)
{
    const int i = blockIdx.x * 256 + threadIdx.x;
    if (i < BB * 3 * NN) out[i] = src[i];
}

// ---------------------------------------------------------------------------
extern "C" void kernel_launch(void* const* d_in, const int* in_sizes, int n_in,
                              void* d_out, int out_size)
{
    const float* src_emb = (const float*)d_in[0];
    const float* tgt_emb = (const float*)d_in[1];
    const float* src     = (const float*)d_in[2];
    const float* tgt     = (const float*)d_in[3];
    const float* Wq      = (const float*)d_in[4];
    const float* bq      = (const float*)d_in[5];
    const float* Wk      = (const float*)d_in[6];
    const float* bk      = (const float*)d_in[7];
    float* out = (float*)d_out;

    const int corr_elems = BB * 3 * NN;
    const bool tuple_out = (out_size >= 2 * corr_elems);
    float* corr_out = tuple_out ? (out + corr_elems) : out;

    splitW_kernel<<<EE * EE / 1024, 256>>>(Wq, 0);
    splitW_kernel<<<EE * EE / 1024, 256>>>(Wk, 1);
    splitX_kernel<<<dim3(NN / 64, EE / 64, BB), 256>>>(src_emb, 0);
    splitX_kernel<<<dim3(MM / 64, EE / 64, BB), 256>>>(tgt_emb, 1);

    cudaFuncSetAttribute(projmma_kernel, cudaFuncAttributeMaxDynamicSharedMemorySize,
                         SMEM_TOTAL);
    projmma_kernel<<<dim3(256, 4), 256, SMEM_TOTAL>>>(bq, 0);
    projmma_kernel<<<dim3(256, 4), 256, SMEM_TOTAL>>>(bk, 1);

    kk_kernel<<<BB * MM / 8, 256>>>();

    cudaFuncSetAttribute(est_kernel, cudaFuncAttributeMaxDynamicSharedMemorySize,
                         P2_TOTAL);
    est_kernel<<<dim3(256, 4), 256, P2_TOTAL>>>();

    gather_kernel<<<BB * NN / 8, 256>>>(tgt, corr_out);

    if (tuple_out)
        copy_src_kernel<<<(corr_elems + 255) / 256, 256>>>(src, out);
}

// round 15
// speedup vs baseline: 1.2549x; 1.2549x over previous
#include <cuda_runtime.h>
#include <cuda_bf16.h>
#include <cuda_fp16.h>
#include <stdint.h>

#define BB 2
#define EE 512
#define NN 4096
#define MM 4096

typedef unsigned long long u64;
typedef unsigned int u32;

// ---- scratch ---------------------------------------------------------------
__device__ __nv_bfloat16 g_Qhi[BB * NN * EE], g_Qlo[BB * NN * EE];
__device__ __nv_bfloat16 g_Khi[BB * MM * EE], g_Klo[BB * MM * EE];
__device__ __nv_bfloat16 g_XQhi[BB * NN * EE], g_XQlo[BB * NN * EE];
__device__ __nv_bfloat16 g_XKhi[BB * MM * EE], g_XKlo[BB * MM * EE];
__device__ __nv_bfloat16 g_Whi[2 * EE * EE], g_Wlo[2 * EE * EE];
__device__ float g_kk[BB * MM];
__device__ __half g_est[(size_t)BB * NN * MM];   // approximate logits (64 MB)

// ---- PTX helpers (portable, no 'a'-features) -------------------------------
__device__ __forceinline__ u32 smem_u32(const void* p) {
    u32 a;
    asm("{ .reg .u64 t; cvta.to.shared.u64 t, %1; cvt.u32.u64 %0, t; }" : "=r"(a) : "l"(p));
    return a;
}
__device__ __forceinline__ void cp16(u32 dst, const void* src) {
    asm volatile("cp.async.cg.shared.global [%0], [%1], 16;" :: "r"(dst), "l"(src) : "memory");
}
#define CP_COMMIT() asm volatile("cp.async.commit_group;" ::: "memory")
#define CP_WAIT0()  asm volatile("cp.async.wait_group 0;" ::: "memory")
#define CP_WAIT1()  asm volatile("cp.async.wait_group 1;" ::: "memory")

__device__ __forceinline__ void ldsm4(u32* r, u32 a) {
    asm volatile("ldmatrix.sync.aligned.m8n8.x4.shared.b16 {%0,%1,%2,%3}, [%4];"
                 : "=r"(r[0]), "=r"(r[1]), "=r"(r[2]), "=r"(r[3]) : "r"(a));
}
__device__ __forceinline__ void mma16816(float* c, const u32* a, const u32* b) {
    asm volatile(
        "mma.sync.aligned.m16n8k16.row.col.f32.bf16.bf16.f32 "
        "{%0,%1,%2,%3}, {%4,%5,%6,%7}, {%8,%9}, {%0,%1,%2,%3};"
        : "+f"(c[0]), "+f"(c[1]), "+f"(c[2]), "+f"(c[3])
        : "r"(a[0]), "r"(a[1]), "r"(a[2]), "r"(a[3]), "r"(b[0]), "r"(b[1]));
}
__device__ __forceinline__ u32 packbf(__nv_bfloat16 a, __nv_bfloat16 b) {
    __nv_bfloat162 t; t.x = a; t.y = b;
    return *reinterpret_cast<u32*>(&t);
}

// ---------------------------------------------------------------------------
// split W: [f][e] fp32 -> bf16 hi/lo
// ---------------------------------------------------------------------------
__global__ __launch_bounds__(256) void splitW_kernel(const float* __restrict__ W, int slot)
{
    const int i = (blockIdx.x * 256 + threadIdx.x) * 4;
    float4 v = *(const float4*)(W + i);
    float x[4] = {v.x, v.y, v.z, v.w};
    __nv_bfloat16 h[4]; float l[4];
#pragma unroll
    for (int k = 0; k < 4; ++k) {
        h[k] = __float2bfloat16_rn(x[k]);
        l[k] = x[k] - __bfloat162float(h[k]);
    }
    uint2 ph, pl;
    ph.x = packbf(h[0], h[1]); ph.y = packbf(h[2], h[3]);
    pl.x = packbf(__float2bfloat16_rn(l[0]), __float2bfloat16_rn(l[1]));
    pl.y = packbf(__float2bfloat16_rn(l[2]), __float2bfloat16_rn(l[3]));
    const size_t off = (size_t)slot * EE * EE + i;
    *(uint2*)(g_Whi + off) = ph;
    *(uint2*)(g_Wlo + off) = pl;
}

// ---------------------------------------------------------------------------
// split+transpose X: [b][e][n] fp32 -> bf16 hi/lo [b][n][e]
// ---------------------------------------------------------------------------
__global__ __launch_bounds__(256) void splitX_kernel(const float* __restrict__ X, int which)
{
    __nv_bfloat16* __restrict__ Yh = which ? g_XKhi : g_XQhi;
    __nv_bfloat16* __restrict__ Yl = which ? g_XKlo : g_XQlo;
    __shared__ float tile[64][65];
    const int tid = threadIdx.x;
    const int n0 = blockIdx.x * 64, e0 = blockIdx.y * 64, b = blockIdx.z;
    const float* Xb = X + (size_t)b * EE * NN;

    const int lr = tid >> 4, n4 = tid & 15;
#pragma unroll
    for (int it = 0; it < 4; ++it) {
        const int e = lr + it * 16;
        float4 v = *(const float4*)(Xb + (size_t)(e0 + e) * NN + n0 + n4 * 4);
        tile[e][n4*4+0] = v.x; tile[e][n4*4+1] = v.y;
        tile[e][n4*4+2] = v.z; tile[e][n4*4+3] = v.w;
    }
    __syncthreads();

    const int n = tid >> 2, et = tid & 3;
    u32 hw[8], lw[8];
#pragma unroll
    for (int k = 0; k < 8; ++k) {
        const float a = tile[et*16 + 2*k][n], c = tile[et*16 + 2*k + 1][n];
        __nv_bfloat16 ha = __float2bfloat16_rn(a), hc = __float2bfloat16_rn(c);
        hw[k] = packbf(ha, hc);
        lw[k] = packbf(__float2bfloat16_rn(a - __bfloat162float(ha)),
                       __float2bfloat16_rn(c - __bfloat162float(hc)));
    }
    const size_t base = ((size_t)b * NN + n0 + n) * EE + e0 + et * 16;
    *(uint4*)(Yh + base)     = *(uint4*)(hw);
    *(uint4*)(Yh + base + 8) = *(uint4*)(hw + 4);
    *(uint4*)(Yl + base)     = *(uint4*)(lw);
    *(uint4*)(Yl + base + 8) = *(uint4*)(lw + 4);
}

// ---------------------------------------------------------------------------
// proj via mma (3-term split), warp-autonomous. Unchanged.
// ---------------------------------------------------------------------------
#define QPITCH 1040
#define SM_QH 0
#define SM_QL 33280
#define SM_K  66560
#define KPITCH 80
#define KLO_OFF 10240
#define STAGE 20480
#define SMEM_TOTAL 107520

__global__ __launch_bounds__(256, 2) void projmma_kernel(const float* __restrict__ bias,
                                                         int which)
{
    extern __shared__ char smraw[];
    const u32 S = smem_u32(smraw);
    const int tid = threadIdx.x, kg = tid >> 5, lane = tid & 31;
    const int b = blockIdx.x >> 7, n0 = (blockIdx.x & 127) * 32;
    const int f0 = blockIdx.y * 128;
    const __nv_bfloat16* Axh = which ? g_XKhi : g_XQhi;
    const __nv_bfloat16* Axl = which ? g_XKlo : g_XQlo;
    __nv_bfloat16* Oh = which ? g_Khi : g_Qhi;
    __nv_bfloat16* Ol = which ? g_Klo : g_Qlo;
    const char* Wh = (const char*)(g_Whi + (size_t)which * EE * EE);
    const char* Wl = (const char*)(g_Wlo + (size_t)which * EE * EE);

    {
        const char* ah = (const char*)(Axh + (size_t)(b * NN + n0) * EE);
        const char* al = (const char*)(Axl + (size_t)(b * NN + n0) * EE);
#pragma unroll
        for (int it = 0; it < 8; ++it) {
            const int i = tid + it * 256;
            const int row = i >> 6, g = (i & 63) * 16;
            cp16(S + SM_QH + row * QPITCH + g, ah + row * 1024 + g);
            cp16(S + SM_QL + row * QPITCH + g, al + row * 1024 + g);
        }
        CP_COMMIT(); CP_WAIT0();
        __syncthreads();
    }

    const int laneQrow = (lane & 7) + ((lane >> 3) & 1) * 8;
    const int laneQcolB = (lane >> 4) * 16;
    const int laneKn = (lane & 7) + ((lane >> 4) & 1) * 8;
    const int laneKeB = ((lane >> 3) & 1) * 16;
    u32 qoff[2];
    qoff[0] = (u32)(laneQrow * QPITCH + laneQcolB);
    qoff[1] = qoff[0] + 16 * QPITCH;
    const u32 koff = (u32)((kg * 16 + laneKn) * KPITCH + laneKeB);

    const u32 fko = (u32)((kg * 16 + (lane >> 1)) * KPITCH + (lane & 1) * 32);
    const char* sWh = Wh + (size_t)(f0 + kg * 16 + (lane >> 1)) * 1024 + (lane & 1) * 32;
    const char* sWl = Wl + (size_t)(f0 + kg * 16 + (lane >> 1)) * 1024 + (lane & 1) * 32;

    float acc[2][2][4];
#pragma unroll
    for (int mt = 0; mt < 2; ++mt)
#pragma unroll
        for (int nt = 0; nt < 2; ++nt)
#pragma unroll
            for (int j = 0; j < 4; ++j) acc[mt][nt][j] = 0.f;

    cp16(S + SM_K + fko,                sWh);
    cp16(S + SM_K + fko + 16,           sWh + 16);
    cp16(S + SM_K + KLO_OFF + fko,      sWl);
    cp16(S + SM_K + KLO_OFF + fko + 16, sWl + 16);
    CP_COMMIT();

    for (int cc = 0; cc < 16; ++cc) {
        if (cc < 15) {
            const int nc = cc + 1;
            const u32 dst = S + SM_K + (u32)(nc & 1) * STAGE + fko;
            const size_t go = (size_t)nc * 64;
            cp16(dst,                sWh + go);
            cp16(dst + 16,           sWh + go + 16);
            cp16(dst + KLO_OFF,      sWl + go);
            cp16(dst + KLO_OFF + 16, sWl + go + 16);
            CP_COMMIT();
            CP_WAIT1();
        } else {
            CP_WAIT0();
        }
        __syncwarp();
        const u32 KB = S + SM_K + (u32)(cc & 1) * STAGE;
        const u32 chB = (u32)(cc * 64);
#pragma unroll
        for (int s = 0; s < 2; ++s) {
            const u32 qeB = chB + (u32)(s * 32);
            const u32 keB = (u32)(s * 32);
            u32 ah[2][4], al[2][4], bh[4], bl[4];
#pragma unroll
            for (int mt = 0; mt < 2; ++mt) {
                ldsm4(ah[mt], S + SM_QH + qoff[mt] + qeB);
                ldsm4(al[mt], S + SM_QL + qoff[mt] + qeB);
            }
            ldsm4(bh, KB + koff + keB);
            ldsm4(bl, KB + KLO_OFF + koff + keB);
#pragma unroll
            for (int mt = 0; mt < 2; ++mt) {
                mma16816(acc[mt][0], ah[mt], &bh[0]);
                mma16816(acc[mt][0], ah[mt], &bl[0]);
                mma16816(acc[mt][0], al[mt], &bh[0]);
                mma16816(acc[mt][1], ah[mt], &bh[2]);
                mma16816(acc[mt][1], ah[mt], &bl[2]);
                mma16816(acc[mt][1], al[mt], &bh[2]);
            }
        }
    }

    __syncthreads();
    float bias2[2][2];
#pragma unroll
    for (int nt = 0; nt < 2; ++nt)
#pragma unroll
        for (int j = 0; j < 2; ++j)
            bias2[nt][j] = __ldg(bias + f0 + kg * 16 + nt * 8 + (lane & 3) * 2 + j);
    __nv_bfloat16* sh = (__nv_bfloat16*)(smraw + SM_K);
    __nv_bfloat16* sl = (__nv_bfloat16*)(smraw + SM_K + 8192);
#pragma unroll
    for (int mt = 0; mt < 2; ++mt)
#pragma unroll
        for (int nt = 0; nt < 2; ++nt)
#pragma unroll
            for (int c = 0; c < 4; ++c) {
                const int row = mt * 16 + (lane >> 2) + (c >> 1) * 8;
                const int col = kg * 16 + nt * 8 + (lane & 3) * 2 + (c & 1);
                const float q = acc[mt][nt][c] + bias2[nt][c & 1];
                const __nv_bfloat16 h = __float2bfloat16_rn(q);
                sh[row * 128 + col] = h;
                sl[row * 128 + col] = __float2bfloat16_rn(q - __bfloat162float(h));
            }
    __syncthreads();
    {
        const int row = tid >> 3, seg = tid & 7;
        const size_t gbase = ((size_t)(b * NN + n0 + row)) * EE + f0 + seg * 16;
        const int sbase = row * 128 + seg * 16;
        *(uint4*)(Oh + gbase)     = *(uint4*)(sh + sbase);
        *(uint4*)(Oh + gbase + 8) = *(uint4*)(sh + sbase + 8);
        *(uint4*)(Ol + gbase)     = *(uint4*)(sl + sbase);
        *(uint4*)(Ol + gbase + 8) = *(uint4*)(sl + sbase + 8);
    }
}

// ---------------------------------------------------------------------------
__global__ __launch_bounds__(256) void kk_kernel()
{
    const int row = blockIdx.x * 8 + (threadIdx.x >> 5);
    const int lane = threadIdx.x & 31;
    const uint4* h4 = (const uint4*)(g_Khi + (size_t)row * EE);
    const uint4* l4 = (const uint4*)(g_Klo + (size_t)row * EE);
    float s = 0.f;
#pragma unroll
    for (int it = 0; it < 2; ++it) {
        uint4 h = h4[lane + it * 32], l = l4[lane + it * 32];
        const __nv_bfloat162* hp = (const __nv_bfloat162*)&h;
        const __nv_bfloat162* lp = (const __nv_bfloat162*)&l;
#pragma unroll
        for (int k = 0; k < 4; ++k) {
            float2 fh = __bfloat1622float2(hp[k]);
            float2 fl = __bfloat1622float2(lp[k]);
            float x = fh.x + fl.x, y = fh.y + fl.y;
            s = fmaf(x, x, fmaf(y, y, s));
        }
    }
#pragma unroll
    for (int off = 16; off; off >>= 1) s += __shfl_xor_sync(0xffffffffu, s, off);
    if (lane == 0) g_kk[row] = s;
}

// ---------------------------------------------------------------------------
// Phase 1 (v3): hi*hi est logits, 64 q-rows per CTA, 32-e chunks (round-12
// pipeline), 2 CTAs/SM. grid (128, 8): b = bx>>6, n-tile = bx&63 (64 rows),
// by = 512-key split. cc<64: tile = cc>>4 (4 x 128 keys), echunk = cc&15.
// ---------------------------------------------------------------------------
#define P3_SMK 66560
#define P3_STAGE 10240
#define P3_TOTAL 87040

__global__ __launch_bounds__(256, 2) void est_kernel()
{
    extern __shared__ char smraw[];
    const u32 S = smem_u32(smraw);
    const int tid = threadIdx.x, kg = tid >> 5, lane = tid & 31;
    const int b = blockIdx.x >> 6, n0 = (blockIdx.x & 63) * 64;
    const int mbase = blockIdx.y * 512;

    {   // Qhi tile fill: 64 rows x 1024 B
        const char* qh = (const char*)(g_Qhi + (size_t)(b * NN + n0) * EE);
#pragma unroll
        for (int it = 0; it < 16; ++it) {
            const int i = tid + it * 256;
            const int row = i >> 6, g = (i & 63) * 16;
            cp16(S + row * QPITCH + g, qh + row * 1024 + g);
        }
        CP_COMMIT(); CP_WAIT0();
        __syncthreads();
    }

    const int laneQrow = (lane & 7) + ((lane >> 3) & 1) * 8;
    const int laneQcolB = (lane >> 4) * 16;
    const int laneKn = (lane & 7) + ((lane >> 4) & 1) * 8;
    const int laneKeB = ((lane >> 3) & 1) * 16;
    u32 qoff[4];
    qoff[0] = (u32)(laneQrow * QPITCH + laneQcolB);
    qoff[1] = qoff[0] + 16 * QPITCH;
    qoff[2] = qoff[0] + 32 * QPITCH;
    qoff[3] = qoff[0] + 48 * QPITCH;
    const u32 koff = (u32)((kg * 16 + laneKn) * KPITCH + laneKeB);
    const u32 fko = (u32)((kg * 16 + (lane >> 1)) * KPITCH + (lane & 1) * 32);
    const char* src_h = (const char*)g_Khi
        + ((size_t)(b * MM + mbase + kg * 16 + (lane >> 1))) * 1024 + (lane & 1) * 32;

    const float* kkb = g_kk + b * MM + mbase;
    __half* estb = g_est + ((size_t)(b * NN + n0)) * MM + mbase;

    float acc[4][2][4];
#pragma unroll
    for (int mt = 0; mt < 4; ++mt)
#pragma unroll
        for (int nt = 0; nt < 2; ++nt)
#pragma unroll
            for (int j = 0; j < 4; ++j) acc[mt][nt][j] = 0.f;

    cp16(S + P3_SMK + fko,      src_h);
    cp16(S + P3_SMK + fko + 16, src_h + 16);
    CP_COMMIT();

    for (int cc = 0; cc < 64; ++cc) {
        if (cc < 63) {
            const int nc = cc + 1;
            const u32 dst = S + P3_SMK + (u32)(nc & 1) * P3_STAGE + fko;
            const size_t go = (size_t)(nc >> 4) * 131072 + (size_t)(nc & 15) * 64;
            cp16(dst,      src_h + go);
            cp16(dst + 16, src_h + go + 16);
            CP_COMMIT();
            CP_WAIT1();
        } else {
            CP_WAIT0();
        }
        __syncwarp();

        const u32 KB = S + P3_SMK + (u32)(cc & 1) * P3_STAGE;
        const u32 chB = (u32)((cc & 15) * 64);
#pragma unroll
        for (int s = 0; s < 2; ++s) {
            u32 ah[4][4], bh[4];
#pragma unroll
            for (int mt = 0; mt < 4; ++mt)
                ldsm4(ah[mt], S + qoff[mt] + chB + (u32)(s * 32));
            ldsm4(bh, KB + koff + (u32)(s * 32));
#pragma unroll
            for (int mt = 0; mt < 4; ++mt) {
                mma16816(acc[mt][0], ah[mt], &bh[0]);
                mma16816(acc[mt][1], ah[mt], &bh[2]);
            }
        }

        if ((cc & 15) == 15) {
            const int m0 = (cc >> 4) * 128;
            const int c0 = kg * 16 + (lane & 3) * 2;
            const float kk0 = __ldg(kkb + m0 + c0);
            const float kk1 = __ldg(kkb + m0 + c0 + 1);
            const float kk2 = __ldg(kkb + m0 + c0 + 8);
            const float kk3 = __ldg(kkb + m0 + c0 + 9);
#pragma unroll
            for (int mt = 0; mt < 4; ++mt)
#pragma unroll
                for (int h = 0; h < 2; ++h) {
                    const int row = mt * 16 + h * 8 + (lane >> 2);
                    __half* ep = estb + (size_t)row * MM + m0 + c0;
                    float2 fa = make_float2(fmaf(2.f, acc[mt][0][h*2+0], -kk0),
                                            fmaf(2.f, acc[mt][0][h*2+1], -kk1));
                    float2 fb = make_float2(fmaf(2.f, acc[mt][1][h*2+0], -kk2),
                                            fmaf(2.f, acc[mt][1][h*2+1], -kk3));
                    *reinterpret_cast<__half2*>(ep)     = __float22half2_rn(fa);
                    *reinterpret_cast<__half2*>(ep + 8) = __float22half2_rn(fb);
                    acc[mt][0][h*2+0] = 0.f; acc[mt][0][h*2+1] = 0.f;
                    acc[mt][1][h*2+0] = 0.f; acc[mt][1][h*2+1] = 0.f;
                }
        }
    }
}

// ---------------------------------------------------------------------------
// Phase 2: register-cached scan + exact recompute. One warp per q-row.
// ---------------------------------------------------------------------------
__global__ __launch_bounds__(256) void gather_kernel(const float* __restrict__ tgt,
                                                     float* __restrict__ out_corr)
{
    const int w = blockIdx.x * 8 + (threadIdx.x >> 5);   // b*NN + n
    const int lane = threadIdx.x & 31;
    const int b = w >> 12, n = w & (NN - 1);

    float qf[16];
    {
        const uint4* qh = (const uint4*)(g_Qhi + (size_t)w * EE + lane * 16);
        const uint4* ql = (const uint4*)(g_Qlo + (size_t)w * EE + lane * 16);
        uint4 H[2] = {qh[0], qh[1]}, L[2] = {ql[0], ql[1]};
#pragma unroll
        for (int g = 0; g < 2; ++g) {
            const __nv_bfloat162* hp = (const __nv_bfloat162*)&H[g];
            const __nv_bfloat162* lp = (const __nv_bfloat162*)&L[g];
#pragma unroll
            for (int j = 0; j < 4; ++j) {
                float2 fh = __bfloat1622float2(hp[j]);
                float2 fl = __bfloat1622float2(lp[j]);
                qf[g*8 + j*2 + 0] = fh.x + fl.x;
                qf[g*8 + j*2 + 1] = fh.y + fl.y;
            }
        }
    }

    const __half* er = g_est + (size_t)w * MM;
    u32 cache[64];
    float rmax = -1e30f;
#pragma unroll
    for (int it = 0; it < 16; ++it) {
        uint4 v = *(const uint4*)(er + it * 256 + lane * 8);
        cache[it*4+0] = v.x; cache[it*4+1] = v.y;
        cache[it*4+2] = v.z; cache[it*4+3] = v.w;
        const __half2* hp = (const __half2*)&v;
#pragma unroll
        for (int j = 0; j < 4; ++j) {
            float2 f = __half22float2(hp[j]);
            rmax = fmaxf(rmax, fmaxf(f.x, f.y));
        }
    }
#pragma unroll
    for (int off = 16; off; off >>= 1)
        rmax = fmaxf(rmax, __shfl_xor_sync(0xffffffffu, rmax, off));
    const float T = rmax - 25.f;

    const float* kkb = g_kk + b * MM;
    const float* tb  = tgt + (size_t)b * 3 * MM;
    float m = -1e30f, sl = 0.f, o0 = 0.f, o1 = 0.f, o2 = 0.f;

#pragma unroll
    for (int it = 0; it < 16; ++it) {
        u32 mk = 0;
#pragma unroll
        for (int j = 0; j < 4; ++j) {
            float2 f = __half22float2(*(const __half2*)&cache[it*4+j]);
            if (f.x >= T) mk |= 1u << (j*2);
            if (f.y >= T) mk |= 1u << (j*2+1);
        }
        u32 wm = __ballot_sync(0xffffffffu, mk != 0);
        while (wm) {
            const int slane = __ffs(wm) - 1;
            wm &= wm - 1;
            u32 m8 = __shfl_sync(0xffffffffu, mk, slane);
            while (m8) {
                const int bit = __ffs(m8) - 1;
                m8 &= m8 - 1;
                const int kix = it * 256 + slane * 8 + bit;
                const uint4* kh = (const uint4*)(g_Khi + (size_t)(b * MM + kix) * EE + lane * 16);
                const uint4* kl = (const uint4*)(g_Klo + (size_t)(b * MM + kix) * EE + lane * 16);
                uint4 H[2] = {kh[0], kh[1]}, L[2] = {kl[0], kl[1]};
                float d = 0.f;
#pragma unroll
                for (int g = 0; g < 2; ++g) {
                    const __nv_bfloat162* hp = (const __nv_bfloat162*)&H[g];
                    const __nv_bfloat162* lp = (const __nv_bfloat162*)&L[g];
#pragma unroll
                    for (int j = 0; j < 4; ++j) {
                        float2 fh = __bfloat1622float2(hp[j]);
                        float2 fl = __bfloat1622float2(lp[j]);
                        d = fmaf(qf[g*8 + j*2 + 0], fh.x + fl.x, d);
                        d = fmaf(qf[g*8 + j*2 + 1], fh.y + fl.y, d);
                    }
                }
#pragma unroll
                for (int off = 16; off; off >>= 1)
                    d += __shfl_xor_sync(0xffffffffu, d, off);
                if (lane == 0) {
                    const float lg = fmaf(2.f, d, -__ldg(kkb + kix));
                    const float nm = fmaxf(m, lg);
                    const float sc = __expf(m - nm);
                    const float p  = __expf(lg - nm);
                    sl = sl * sc + p;
                    o0 = o0 * sc + p * __ldg(tb + kix);
                    o1 = o1 * sc + p * __ldg(tb + MM + kix);
                    o2 = o2 * sc + p * __ldg(tb + 2 * MM + kix);
                    m = nm;
                }
            }
        }
    }

    if (lane == 0) {
        const float inv = 1.f / sl;
        out_corr[(size_t)b * 3 * NN + n]          = o0 * inv;
        out_corr[(size_t)b * 3 * NN + NN + n]     = o1 * inv;
        out_corr[(size_t)b * 3 * NN + 2 * NN + n] = o2 * inv;
    }
}

__global__ void copy_src_kernel(const float* __restrict__ src, float* __restrict__ out)
{
    const int i = blockIdx.x * 256 + threadIdx.x;
    if (i < BB * 3 * NN) out[i] = src[i];
}

// ---------------------------------------------------------------------------
extern "C" void kernel_launch(void* const* d_in, const int* in_sizes, int n_in,
                              void* d_out, int out_size)
{
    const float* src_emb = (const float*)d_in[0];
    const float* tgt_emb = (const float*)d_in[1];
    const float* src     = (const float*)d_in[2];
    const float* tgt     = (const float*)d_in[3];
    const float* Wq      = (const float*)d_in[4];
    const float* bq      = (const float*)d_in[5];
    const float* Wk      = (const float*)d_in[6];
    const float* bk      = (const float*)d_in[7];
    float* out = (float*)d_out;

    const int corr_elems = BB * 3 * NN;
    const bool tuple_out = (out_size >= 2 * corr_elems);
    float* corr_out = tuple_out ? (out + corr_elems) : out;

    splitW_kernel<<<EE * EE / 1024, 256>>>(Wq, 0);
    splitW_kernel<<<EE * EE / 1024, 256>>>(Wk, 1);
    splitX_kernel<<<dim3(NN / 64, EE / 64, BB), 256>>>(src_emb, 0);
    splitX_kernel<<<dim3(MM / 64, EE / 64, BB), 256>>>(tgt_emb, 1);

    cudaFuncSetAttribute(projmma_kernel, cudaFuncAttributeMaxDynamicSharedMemorySize,
                         SMEM_TOTAL);
    projmma_kernel<<<dim3(256, 4), 256, SMEM_TOTAL>>>(bq, 0);
    projmma_kernel<<<dim3(256, 4), 256, SMEM_TOTAL>>>(bk, 1);

    kk_kernel<<<BB * MM / 8, 256>>>();

    cudaFuncSetAttribute(est_kernel, cudaFuncAttributeMaxDynamicSharedMemorySize,
                         P3_TOTAL);
    est_kernel<<<dim3(128, 8), 256, P3_TOTAL>>>();

    gather_kernel<<<BB * NN / 8, 256>>>(tgt, corr_out);

    if (tuple_out)
        copy_src_kernel<<<(corr_elems + 255) / 256, 256>>>(src, out);
}